// round 2
// baseline (speedup 1.0000x reference)
#include <cuda_runtime.h>
#include <cuda_bf16.h>
#include <cooperative_groups.h>

namespace cg = cooperative_groups;

#define N_ST   512
#define N_OBSV 1024
#define BATCH  64
#define TMAXL  512
#define CLUSTER_N 4
#define ROWS_PER_CTA 128   /* N_ST / CLUSTER_N */
#define BPG 2              /* batches per cluster group */
#define THREADS 256

/* ---- device scratch (no allocs allowed) ---- */
__device__ __nv_bfloat16 g_Pt[N_ST * N_ST];   /* packed: ((k>>2)*512 + i)*4 + (k&3) */
__device__ float g_logET[N_OBSV * N_ST];      /* [obs][state] */
__device__ float g_logPi[N_ST];
__device__ float g_icolsum[N_ST];

/* ---------------- prep kernels (one-time, cheap) ---------------- */

__global__ void prep_logpi(const float* __restrict__ pi) {
    __shared__ float red[8];
    int tid = threadIdx.x;
    float s = 0.f;
    for (int k = tid; k < N_ST; k += 256) s += __expf(pi[k]);
    for (int o = 16; o; o >>= 1) s += __shfl_xor_sync(0xffffffffu, s, o);
    if ((tid & 31) == 0) red[tid >> 5] = s;
    __syncthreads();
    float tot = 0.f;
    #pragma unroll
    for (int w = 0; w < 8; w++) tot += red[w];
    float l = __logf(tot);
    for (int k = tid; k < N_ST; k += 256) g_logPi[k] = pi[k] - l;
}

/* colsum[k] = sum_i exp(A[i,k]); grid 16 x 256 threads (32 kx, 8 iy) */
__global__ void prep_colsum(const float* __restrict__ A) {
    __shared__ float part[8][32];
    int kx = threadIdx.x & 31, iy = threadIdx.x >> 5;
    int k = blockIdx.x * 32 + kx;
    float s = 0.f;
    for (int i = iy; i < N_ST; i += 8) s += __expf(A[i * N_ST + k]);
    part[iy][kx] = s;
    __syncthreads();
    if (iy == 0) {
        float t = 0.f;
        #pragma unroll
        for (int j = 0; j < 8; j++) t += part[j][kx];
        g_icolsum[k] = 1.0f / t;
    }
}

/* P[i,k] = exp(A[i,k]) / colsum[k], stored bf16 in packed transposed layout */
__global__ void prep_pt(const float* __restrict__ A) {
    int i = blockIdx.x;
    for (int k = threadIdx.x; k < N_ST; k += 256) {
        float p = __expf(A[i * N_ST + k]) * g_icolsum[k];
        int kk = k >> 2, j = k & 3;
        g_Pt[(kk * N_ST + i) * 4 + j] = __float2bfloat16(p);
    }
}

/* log_ET[o][i] = E[i][o] - log(sum_o exp(E[i][o])) */
__global__ void prep_logE(const float* __restrict__ E) {
    __shared__ float red[8];
    int i = blockIdx.x;
    int tid = threadIdx.x;
    float s = 0.f;
    for (int o = tid; o < N_OBSV; o += 256) s += __expf(E[i * N_OBSV + o]);
    for (int o = 16; o; o >>= 1) s += __shfl_xor_sync(0xffffffffu, s, o);
    if ((tid & 31) == 0) red[tid >> 5] = s;
    __syncthreads();
    float tot = 0.f;
    #pragma unroll
    for (int w = 0; w < 8; w++) tot += red[w];
    float l = __logf(tot);
    for (int o = tid; o < N_OBSV; o += 256)
        g_logET[o * N_ST + i] = E[i * N_OBSV + o] - l;
}

/* ---------------- main persistent clustered kernel ---------------- */

#define PS_BYTES   131072               /* 512k x 128i bf16 (as 16384 u64) */
#define ALPHA_OFF  PS_BYTES             /* float [2 buf][2 b][512] = 8192 B */
#define W_OFF      (ALPHA_OFF + 8192)   /* float [2 b][512] = 4096 B       */
#define RED_OFF    (W_OFF + 4096)       /* float [16]                      */
#define SMEM_TOTAL (RED_OFF + 64)

extern __shared__ unsigned char smem_raw[];

__global__ void __cluster_dims__(CLUSTER_N, 1, 1) __launch_bounds__(THREADS, 1)
hmm_main(const int* __restrict__ x, const int* __restrict__ Tarr,
         float* __restrict__ out)
{
    cg::cluster_group cluster = cg::this_cluster();
    const unsigned rank = cluster.block_rank();
    const unsigned grp  = blockIdx.x / CLUSTER_N;

    unsigned long long* Ps = (unsigned long long*)smem_raw;
    float* alpha = (float*)(smem_raw + ALPHA_OFF);  /* [buf][b][512] */
    float* wsh   = (float*)(smem_raw + W_OFF);      /* [b][512]      */
    float* red   = (float*)(smem_raw + RED_OFF);    /* [16]          */

    const int tid = threadIdx.x;
    const int b   = tid >> 7;      /* 0/1 */
    const int il  = tid & 127;
    const int bg  = grp * BPG + b;
    const int iglob = rank * ROWS_PER_CTA + il;

    /* load this CTA's P slice into smem (coalesced u64 loads) */
    const unsigned long long* Pg = (const unsigned long long*)g_Pt;
    for (int s = tid; s < 128 * ROWS_PER_CTA; s += THREADS) {
        int kk = s >> 7, il2 = s & 127;
        Ps[s] = Pg[kk * N_ST + rank * ROWS_PER_CTA + il2];
    }

    const int T0 = Tarr[grp * BPG + 0];
    const int T1 = Tarr[grp * BPG + 1];
    const int Tc = max(T0, T1);
    const int myT = (b == 0) ? T0 : T1;

    /* alpha_0, full, replicated per CTA */
    {
        int xv = x[bg * TMAXL + 0];
        const float* em = &g_logET[xv * N_ST];
        #pragma unroll
        for (int j = 0; j < 4; j++) {
            int k = il + 128 * j;
            alpha[b * N_ST + k] = g_logPi[k] + em[k];
        }
    }
    __syncthreads();

    for (int t = 0; t < Tc; ++t) {
        const int buf = t & 1;
        const float* a = alpha + buf * (2 * N_ST) + b * N_ST;

        /* m = max_k alpha[b,k] */
        float lm = -3.402823466e38f;
        #pragma unroll
        for (int j = 0; j < 4; j++) lm = fmaxf(lm, a[il + 128 * j]);
        #pragma unroll
        for (int o = 16; o; o >>= 1) lm = fmaxf(lm, __shfl_xor_sync(0xffffffffu, lm, o));
        if ((tid & 31) == 0) red[tid >> 5] = lm;
        __syncthreads();
        const float m = fmaxf(fmaxf(red[b * 4 + 0], red[b * 4 + 1]),
                              fmaxf(red[b * 4 + 2], red[b * 4 + 3]));
        __syncthreads();

        /* w = exp(alpha - m), sumw */
        float ls = 0.f;
        #pragma unroll
        for (int j = 0; j < 4; j++) {
            int k = il + 128 * j;
            float wv = __expf(a[k] - m);
            wsh[b * N_ST + k] = wv;
            ls += wv;
        }
        #pragma unroll
        for (int o = 16; o; o >>= 1) ls += __shfl_xor_sync(0xffffffffu, ls, o);
        if ((tid & 31) == 0) red[tid >> 5] = ls;
        __syncthreads();
        const float sumw = red[b * 4 + 0] + red[b * 4 + 1] + red[b * 4 + 2] + red[b * 4 + 3];

        /* emit result when this batch's sequence ends */
        if (t == myT - 1 && rank == 0 && il == 0)
            out[bg] = m + __logf(sumw);

        if (t == Tc - 1) break;

        /* emission for t+1 (coalesced gather from transposed log_E) */
        const int xv = x[bg * TMAXL + (t + 1)];
        const float em = g_logET[xv * N_ST + iglob];

        /* dot: sum_k P[iglob,k] * w[b,k]   (bf16 P, fp32 accum, 4 chains) */
        const float4* wq = (const float4*)&wsh[b * N_ST];
        float acc0 = 0.f, acc1 = 0.f, acc2 = 0.f, acc3 = 0.f;
        #pragma unroll 8
        for (int kk = 0; kk < 128; ++kk) {
            unsigned long long pu = Ps[kk * 128 + il];
            float4 wv = wq[kk];
            unsigned lo = (unsigned)pu, hi = (unsigned)(pu >> 32);
            acc0 += __uint_as_float(lo << 16)          * wv.x;
            acc1 += __uint_as_float(lo & 0xffff0000u)  * wv.y;
            acc2 += __uint_as_float(hi << 16)          * wv.z;
            acc3 += __uint_as_float(hi & 0xffff0000u)  * wv.w;
        }
        const float dot = (acc0 + acc1) + (acc2 + acc3);
        const float nv = em + m + __logf(dot);

        /* exchange slice into every rank's next alpha buffer (DSMEM) */
        const int nb = 1 - buf;
        float* dstBase = alpha + nb * (2 * N_ST) + b * N_ST + iglob;
        #pragma unroll
        for (int dr = 0; dr < CLUSTER_N; ++dr) {
            float* p = cluster.map_shared_rank(dstBase, dr);
            *p = nv;
        }
        cluster.sync();
    }
}

/* ---------------- launch ---------------- */

extern "C" void kernel_launch(void* const* d_in, const int* in_sizes, int n_in,
                              void* d_out, int out_size)
{
    const float* pi = (const float*)d_in[0];
    const float* A  = (const float*)d_in[1];
    const float* E  = (const float*)d_in[2];
    const int*   x  = (const int*)d_in[3];
    const int*   T  = (const int*)d_in[4];
    float* out = (float*)d_out;

    cudaFuncSetAttribute(hmm_main, cudaFuncAttributeMaxDynamicSharedMemorySize, SMEM_TOTAL);

    prep_logpi<<<1, 256>>>(pi);
    prep_colsum<<<16, 256>>>(A);
    prep_pt<<<N_ST, 256>>>(A);
    prep_logE<<<N_ST, 256>>>(E);
    hmm_main<<<BATCH / BPG * CLUSTER_N, THREADS, SMEM_TOTAL>>>(x, T, out);
}

// round 3
// speedup vs baseline: 1.2501x; 1.2501x over previous
#include <cuda_runtime.h>
#include <cuda_bf16.h>
#include <cooperative_groups.h>

namespace cg = cooperative_groups;

#define N_ST   512
#define N_OBSV 1024
#define BATCH  64
#define TMAXL  512
#define CLUSTER_N 4
#define THREADS 256

/* ---- device scratch (no allocs) ---- */
__device__ uint4 g_P8[64 * N_ST];        /* [kgroup g][row i]: 8 bf16-pair-packed P[i, 8g..8g+7] */
__device__ float g_logET[N_OBSV * N_ST]; /* [obs][state] log emission  */
__device__ float g_expET[N_OBSV * N_ST]; /* [obs][state] emission prob */
__device__ float g_logPi[N_ST];
__device__ float g_icolsum[N_ST];

/* ---------------- prep kernels ---------------- */

__global__ void prep_logpi(const float* __restrict__ pi) {
    __shared__ float red[8];
    int tid = threadIdx.x;
    float s = 0.f;
    for (int k = tid; k < N_ST; k += 256) s += __expf(pi[k]);
    for (int o = 16; o; o >>= 1) s += __shfl_xor_sync(0xffffffffu, s, o);
    if ((tid & 31) == 0) red[tid >> 5] = s;
    __syncthreads();
    float tot = 0.f;
    #pragma unroll
    for (int w = 0; w < 8; w++) tot += red[w];
    float l = __logf(tot);
    for (int k = tid; k < N_ST; k += 256) g_logPi[k] = pi[k] - l;
}

__global__ void prep_colsum(const float* __restrict__ A) {
    __shared__ float part[8][32];
    int kx = threadIdx.x & 31, iy = threadIdx.x >> 5;
    int k = blockIdx.x * 32 + kx;
    float s = 0.f;
    for (int i = iy; i < N_ST; i += 8) s += __expf(A[i * N_ST + k]);
    part[iy][kx] = s;
    __syncthreads();
    if (iy == 0) {
        float t = 0.f;
        #pragma unroll
        for (int j = 0; j < 8; j++) t += part[j][kx];
        g_icolsum[k] = 1.0f / t;
    }
}

/* pack pair (pe,po): low16 = bf16(pe); high16 chosen so that the full u32,
   reinterpreted as f32, is the nearest representation of po given the fixed
   low bits (unbiased +-2^-9). pe recovered exactly via (q<<16).          */
__device__ __forceinline__ unsigned pack_pair(float pe, float po) {
    unsigned lo = (unsigned)__bfloat16_as_ushort(__float2bfloat16(pe));
    unsigned ob = __float_as_uint(po);
    unsigned hi = (ob - lo + 0x8000u) >> 16;
    return lo | (hi << 16);
}

__global__ void prep_pt(const float* __restrict__ A) {
    int i = blockIdx.x;       /* row   */
    int g = threadIdx.x;      /* 64 k-groups */
    float p[8];
    #pragma unroll
    for (int j = 0; j < 8; j++) {
        int k = g * 8 + j;
        p[j] = __expf(A[i * N_ST + k]) * g_icolsum[k];
    }
    uint4 q;
    q.x = pack_pair(p[0], p[1]);
    q.y = pack_pair(p[2], p[3]);
    q.z = pack_pair(p[4], p[5]);
    q.w = pack_pair(p[6], p[7]);
    g_P8[g * N_ST + i] = q;
}

__global__ void prep_logE(const float* __restrict__ E) {
    __shared__ float red[8];
    int i = blockIdx.x;
    int tid = threadIdx.x;
    float s = 0.f;
    for (int o = tid; o < N_OBSV; o += 256) s += __expf(E[i * N_OBSV + o]);
    for (int o = 16; o; o >>= 1) s += __shfl_xor_sync(0xffffffffu, s, o);
    if ((tid & 31) == 0) red[tid >> 5] = s;
    __syncthreads();
    float tot = 0.f;
    #pragma unroll
    for (int w = 0; w < 8; w++) tot += red[w];
    float l = __logf(tot);
    for (int o = tid; o < N_OBSV; o += 256) {
        float lv = E[i * N_OBSV + o] - l;
        g_logET[o * N_ST + i] = lv;
        g_expET[o * N_ST + i] = __expf(lv);
    }
}

/* ---------------- main persistent clustered kernel ---------------- */

#define U_STRIDE 544                       /* floats per (buf,b): 512 state + 16 partial + pad */
#define U_OFF    131072                    /* after P slice (64*128*16 B) */
#define PD_OFF   (U_OFF + 2*2*U_STRIDE*4)  /* 148480 */
#define RED_OFF  (PD_OFF + 2*2*128*4)      /* 150528 */
#define SMEM_TOTAL (RED_OFF + 128)         /* 150656 */

extern __shared__ unsigned char smem_raw[];

__global__ void __cluster_dims__(CLUSTER_N, 1, 1) __launch_bounds__(THREADS, 1)
hmm_main(const int* __restrict__ x, const int* __restrict__ Tarr,
         float* __restrict__ out)
{
    cg::cluster_group cluster = cg::this_cluster();
    const unsigned rank = cluster.block_rank();
    const unsigned grp  = blockIdx.x / CLUSTER_N;

    uint4* P8s  = (uint4*)smem_raw;                  /* [g*128 + il] */
    float* uarr = (float*)(smem_raw + U_OFF);        /* [(buf*2+b)*U_STRIDE + .] */
    float* pdot = (float*)(smem_raw + PD_OFF);       /* [(kh*2+b)*128 + il] */
    float* red  = (float*)(smem_raw + RED_OFF);

    const int tid  = threadIdx.x;
    const int il   = tid & 127;
    const int hi2  = tid >> 7;        /* kh in dot phase; b in scalar phases */
    const int warp = tid >> 5;
    const int lane = tid & 31;
    const int iglob = rank * 128 + il;

    /* load P slice (coalesced 16B) */
    for (int s = tid; s < 64 * 128; s += THREADS) {
        int g = s >> 7, r2 = s & 127;
        P8s[s] = g_P8[g * N_ST + rank * 128 + r2];
    }

    const int T0v = Tarr[grp * 2 + 0];
    const int T1v = Tarr[grp * 2 + 1];
    const int Tc  = max(T0v, T1v);

    /* ---- init: u_0 = exp(alpha0 - m), fully local & replicated ---- */
    float C0, C1;
    {
        int x0 = x[(grp * 2 + hi2) * TMAXL];
        float a[4];
        float lm = -3.402823466e38f;
        #pragma unroll
        for (int j = 0; j < 4; j++) {
            int s = il + 128 * j;
            a[j] = g_logPi[s] + g_logET[x0 * N_ST + s];
            lm = fmaxf(lm, a[j]);
        }
        #pragma unroll
        for (int o = 16; o; o >>= 1) lm = fmaxf(lm, __shfl_xor_sync(0xffffffffu, lm, o));
        if (lane == 0) red[warp] = lm;
        __syncthreads();
        const float m0 = fmaxf(fmaxf(red[0], red[1]), fmaxf(red[2], red[3]));
        const float m1 = fmaxf(fmaxf(red[4], red[5]), fmaxf(red[6], red[7]));
        C0 = m0; C1 = m1;
        const float m = hi2 ? m1 : m0;
        float* u0b = uarr + hi2 * U_STRIDE;   /* buf 0 */
        float ls = 0.f;
        #pragma unroll
        for (int j = 0; j < 4; j++) {
            int s = il + 128 * j;
            float uv = __expf(a[j] - m);
            u0b[s] = uv;
            ls += uv;
        }
        #pragma unroll
        for (int o = 16; o; o >>= 1) ls += __shfl_xor_sync(0xffffffffu, ls, o);
        if (lane == 0) u0b[512 + (warp & 3)] = ls;          /* 4 warp partials */
        if (il >= 4 && il < 16) u0b[512 + il] = 0.f;        /* zero slots 516..527 */
        __syncthreads();
    }

    for (int t = 0; t < Tc; ++t) {
        const int buf = t & 1;
        float* ub0 = uarr + (buf * 2 + 0) * U_STRIDE;
        float* ub1 = uarr + (buf * 2 + 1) * U_STRIDE;

        /* S = sum of 16 partials per batch (uniform) */
        float4 p0a = *(const float4*)(ub0 + 512), p0b = *(const float4*)(ub0 + 516);
        float4 p0c = *(const float4*)(ub0 + 520), p0d = *(const float4*)(ub0 + 524);
        float4 p1a = *(const float4*)(ub1 + 512), p1b = *(const float4*)(ub1 + 516);
        float4 p1c = *(const float4*)(ub1 + 520), p1d = *(const float4*)(ub1 + 524);
        const float S0 = (((p0a.x + p0a.y) + (p0a.z + p0a.w)) + ((p0b.x + p0b.y) + (p0b.z + p0b.w)))
                       + (((p0c.x + p0c.y) + (p0c.z + p0c.w)) + ((p0d.x + p0d.y) + (p0d.z + p0d.w)));
        const float S1 = (((p1a.x + p1a.y) + (p1a.z + p1a.w)) + ((p1b.x + p1b.y) + (p1b.z + p1b.w)))
                       + (((p1c.x + p1c.y) + (p1c.z + p1c.w)) + ((p1d.x + p1d.y) + (p1d.z + p1d.w)));
        C0 += __logf(S0);
        C1 += __logf(S1);

        if (rank == 0 && tid == 0) {
            if (t == T0v - 1) out[grp * 2 + 0] = C0;
            if (t == T1v - 1) out[grp * 2 + 1] = C1;
        }
        if (t == Tc - 1) break;

        /* prefetch emission for phase-2 identity (b = hi2) */
        const int   xv   = x[(grp * 2 + hi2) * TMAXL + t + 1];
        const float em   = g_expET[xv * N_ST + iglob];
        const float invS = __frcp_rn(hi2 ? S1 : S0);

        /* ---- dot phase: this thread = (row il, k-half hi2), both batches ---- */
        const uint4*  Pp = P8s + (hi2 * 32) * 128 + il;
        const float4* w0 = (const float4*)(ub0 + hi2 * 256);
        const float4* w1 = (const float4*)(ub1 + hi2 * 256);
        float ae0 = 0.f, ae1 = 0.f, ae2 = 0.f, ae3 = 0.f;
        float ao0 = 0.f, ao1 = 0.f, ao2 = 0.f, ao3 = 0.f;
        float be0 = 0.f, be1 = 0.f, be2 = 0.f, be3 = 0.f;
        float bo0 = 0.f, bo1 = 0.f, bo2 = 0.f, bo3 = 0.f;
        #pragma unroll 8
        for (int gg = 0; gg < 32; ++gg) {
            uint4 q = Pp[gg * 128];
            float4 wA0 = w0[gg * 2], wB0 = w0[gg * 2 + 1];
            float4 wA1 = w1[gg * 2], wB1 = w1[gg * 2 + 1];
            float f0e = __uint_as_float(q.x << 16), f0o = __uint_as_float(q.x);
            float f1e = __uint_as_float(q.y << 16), f1o = __uint_as_float(q.y);
            float f2e = __uint_as_float(q.z << 16), f2o = __uint_as_float(q.z);
            float f3e = __uint_as_float(q.w << 16), f3o = __uint_as_float(q.w);
            ae0 += f0e * wA0.x;  ao0 += f0o * wA0.y;
            ae1 += f1e * wA0.z;  ao1 += f1o * wA0.w;
            ae2 += f2e * wB0.x;  ao2 += f2o * wB0.y;
            ae3 += f3e * wB0.z;  ao3 += f3o * wB0.w;
            be0 += f0e * wA1.x;  bo0 += f0o * wA1.y;
            be1 += f1e * wA1.z;  bo1 += f1o * wA1.w;
            be2 += f2e * wB1.x;  bo2 += f2o * wB1.y;
            be3 += f3e * wB1.z;  bo3 += f3o * wB1.w;
        }
        pdot[(hi2 * 2 + 0) * 128 + il] =
            ((ae0 + ao0) + (ae1 + ao1)) + ((ae2 + ao2) + (ae3 + ao3));
        pdot[(hi2 * 2 + 1) * 128 + il] =
            ((be0 + bo0) + (be1 + bo1)) + ((be2 + bo2) + (be3 + bo3));
        __syncthreads();

        /* ---- phase 2: this thread = (batch hi2, row il) ---- */
        const float d = pdot[(0 * 2 + hi2) * 128 + il] + pdot[(1 * 2 + hi2) * 128 + il];
        const float v = em * d * invS;

        float ps = v;
        #pragma unroll
        for (int o = 16; o; o >>= 1) ps += __shfl_xor_sync(0xffffffffu, ps, o);

        /* exchange slice + warp partial to all ranks (DSMEM) */
        const int nb = buf ^ 1;
        float* dst   = uarr + (nb * 2 + hi2) * U_STRIDE + iglob;
        float* dslot = uarr + (nb * 2 + hi2) * U_STRIDE + 512 + rank * 4 + (warp & 3);
        #pragma unroll
        for (int dr = 0; dr < CLUSTER_N; ++dr) {
            *cluster.map_shared_rank(dst, dr) = v;
            if (lane == 0) *cluster.map_shared_rank(dslot, dr) = ps;
        }
        cluster.sync();
    }
}

/* ---------------- launch ---------------- */

extern "C" void kernel_launch(void* const* d_in, const int* in_sizes, int n_in,
                              void* d_out, int out_size)
{
    const float* pi = (const float*)d_in[0];
    const float* A  = (const float*)d_in[1];
    const float* E  = (const float*)d_in[2];
    const int*   x  = (const int*)d_in[3];
    const int*   T  = (const int*)d_in[4];
    float* out = (float*)d_out;

    cudaFuncSetAttribute(hmm_main, cudaFuncAttributeMaxDynamicSharedMemorySize, SMEM_TOTAL);

    prep_logpi<<<1, 256>>>(pi);
    prep_colsum<<<16, 256>>>(A);
    prep_pt<<<N_ST, 64>>>(A);
    prep_logE<<<N_ST, 256>>>(E);
    hmm_main<<<(BATCH / 2) * CLUSTER_N, THREADS, SMEM_TOTAL>>>(x, T, out);
}

// round 6
// speedup vs baseline: 1.7032x; 1.3624x over previous
#include <cuda_runtime.h>
#include <cuda_bf16.h>
#include <cooperative_groups.h>

namespace cg = cooperative_groups;

#define N_ST   512
#define N_OBSV 1024
#define BATCH  64
#define TMAXL  512
#define CLUSTER_N 4
#define THREADS 256

/* ---- device scratch (no allocs) ---- */
/* g_P4[kp*128 + rank*32 + rg] : uint4 = rows (4rg..4rg+3) of CTA 'rank',
   each u32 = compensation-packed pair (P[r][2kp], P[r][2kp+1])            */
__device__ uint4 g_P4[256 * 128];
__device__ float g_logET[N_OBSV * N_ST]; /* [obs][state] log emission  */
__device__ float g_expET[N_OBSV * N_ST]; /* [obs][state] emission prob */
__device__ float g_logPi[N_ST];
__device__ float g_icolsum[N_ST];

/* ---------------- PTX helpers ---------------- */

__device__ __forceinline__ unsigned s2u(const void* p) {
    return (unsigned)__cvta_generic_to_shared(p);
}

#define FMA2(acc, a, w) \
    asm("fma.rn.f32x2 %0, %1, %2, %0;" : "+l"(acc) : "l"(a), "l"(w))

#define MBARRIER_INIT(mbar, count) \
    asm volatile("mbarrier.init.shared.b64 [%0], %1;" \
        :: "r"(mbar), "r"((unsigned)(count)) : "memory")

#define MBARRIER_ARRIVE_CLUSTER(local_mbar, target_rank) \
    asm volatile( \
        "{\n\t" \
        ".reg .b32 remAddr32;\n\t" \
        "mapa.shared::cluster.u32 remAddr32, %0, %1;\n\t" \
        "mbarrier.arrive.release.cluster.shared::cluster.b64 _, [remAddr32];\n\t" \
        "}" \
        :: "r"(local_mbar), "r"((unsigned)(target_rank)) : "memory")

#define MBARRIER_WAIT_PARITY(mbar, parity) do { \
    unsigned _m = (mbar), _p = (parity), _done; \
    asm volatile( \
        "{\n\t.reg .pred p;\n\t" \
        "mbarrier.try_wait.parity.acquire.cta.shared::cta.b64 p, [%1], %2;\n\t" \
        "selp.b32 %0, 1, 0, p;\n\t}" \
        : "=r"(_done) : "r"(_m), "r"(_p) : "memory"); \
    if (!_done) { \
        asm volatile( \
            "{\n\t.reg .pred P1;\n\t" \
            "WL_%=:\n\t" \
            "mbarrier.try_wait.parity.acquire.cta.shared::cta.b64 P1, [%0], %1, 0x989680;\n\t" \
            "@P1 bra.uni WD_%=;\n\t" \
            "bra.uni WL_%=;\n\t" \
            "WD_%=:\n\t}" \
            :: "r"(_m), "r"(_p) : "memory"); \
    } \
} while (0)

/* ---------------- prep kernels ---------------- */

__global__ void prep_logpi(const float* __restrict__ pi) {
    __shared__ float red[8];
    int tid = threadIdx.x;
    float s = 0.f;
    for (int k = tid; k < N_ST; k += 256) s += __expf(pi[k]);
    for (int o = 16; o; o >>= 1) s += __shfl_xor_sync(0xffffffffu, s, o);
    if ((tid & 31) == 0) red[tid >> 5] = s;
    __syncthreads();
    float tot = 0.f;
    #pragma unroll
    for (int w = 0; w < 8; w++) tot += red[w];
    float l = __logf(tot);
    for (int k = tid; k < N_ST; k += 256) g_logPi[k] = pi[k] - l;
}

__global__ void prep_colsum(const float* __restrict__ A) {
    __shared__ float part[8][32];
    int kx = threadIdx.x & 31, iy = threadIdx.x >> 5;
    int k = blockIdx.x * 32 + kx;
    float s = 0.f;
    for (int i = iy; i < N_ST; i += 8) s += __expf(A[i * N_ST + k]);
    part[iy][kx] = s;
    __syncthreads();
    if (iy == 0) {
        float t = 0.f;
        #pragma unroll
        for (int j = 0; j < 8; j++) t += part[j][kx];
        g_icolsum[k] = 1.0f / t;
    }
}

/* low16 = bf16(pe) (recovered exactly via <<16); high16 rounded at prep so the
   raw u32 reinterpreted as f32 is the nearest repr of po given fixed low bits */
__device__ __forceinline__ unsigned pack_pair(float pe, float po) {
    unsigned lo = (unsigned)__bfloat16_as_ushort(__float2bfloat16(pe));
    unsigned ob = __float_as_uint(po);
    unsigned hi = (ob - lo + 0x8000u) >> 16;
    return lo | (hi << 16);
}

__global__ void prep_pt(const float* __restrict__ A) {
    int i  = blockIdx.x;        /* row  */
    int kp = threadIdx.x;       /* 0..255 k-pair */
    float p0 = __expf(A[i * N_ST + 2 * kp])     * g_icolsum[2 * kp];
    float p1 = __expf(A[i * N_ST + 2 * kp + 1]) * g_icolsum[2 * kp + 1];
    int rank = i >> 7, rg = (i >> 2) & 31, j = i & 3;
    ((unsigned*)g_P4)[((kp * 128) + rank * 32 + rg) * 4 + j] = pack_pair(p0, p1);
}

__global__ void prep_logE(const float* __restrict__ E) {
    __shared__ float red[8];
    int i = blockIdx.x;
    int tid = threadIdx.x;
    float s = 0.f;
    for (int o = tid; o < N_OBSV; o += 256) s += __expf(E[i * N_OBSV + o]);
    for (int o = 16; o; o >>= 1) s += __shfl_xor_sync(0xffffffffu, s, o);
    if ((tid & 31) == 0) red[tid >> 5] = s;
    __syncthreads();
    float tot = 0.f;
    #pragma unroll
    for (int w = 0; w < 8; w++) tot += red[w];
    float l = __logf(tot);
    for (int o = tid; o < N_OBSV; o += 256) {
        float lv = E[i * N_OBSV + o] - l;
        g_logET[o * N_ST + i] = lv;
        g_expET[o * N_ST + i] = __expf(lv);
    }
}

/* ---------------- main persistent clustered kernel ---------------- */

#define U_STRIDE 544                        /* floats: 512 u + 16 partials + pad */
#define P_BYTES  131072
#define U_OFF    P_BYTES
#define PD_OFF   (U_OFF + 2 * 2 * U_STRIDE * 4)   /* 148480 */
#define BAR_OFF  (PD_OFF + 16 * 128 * 4)          /* 156672 */
#define RED_OFF  (BAR_OFF + 16)
#define SMEM_TOTAL (RED_OFF + 64)

extern __shared__ unsigned char smem_raw[];

__global__ void __cluster_dims__(CLUSTER_N, 1, 1) __launch_bounds__(THREADS, 1)
hmm_main(const int* __restrict__ x, const int* __restrict__ Tarr,
         float* __restrict__ out)
{
    cg::cluster_group cluster = cg::this_cluster();
    const unsigned rank = cluster.block_rank();
    const unsigned grp  = blockIdx.x / CLUSTER_N;

    uint4* Ps   = (uint4*)smem_raw;                 /* [kp*32 + rg]            */
    float* uarr = (float*)(smem_raw + U_OFF);       /* [(buf*2+b)*U_STRIDE+.]  */
    float* pdot = (float*)(smem_raw + PD_OFF);      /* [(ks*2+b)*128 + il]     */
    float* red  = (float*)(smem_raw + RED_OFF);
    const unsigned bar0 = s2u(smem_raw + BAR_OFF);
    const unsigned bar1 = bar0 + 8;

    const int tid  = threadIdx.x;
    const int lane = tid & 31;
    const int warp = tid >> 5;
    const int b    = tid >> 7;        /* batch id in scalar phases */
    const int il   = tid & 127;
    const int iglob = rank * 128 + il;

    if (tid == 0) { MBARRIER_INIT(bar0, CLUSTER_N); MBARRIER_INIT(bar1, CLUSTER_N); }

    /* load P slice (coalesced 16B) */
    for (int s = tid; s < 8192; s += THREADS) {
        int kp = s >> 5, rg = s & 31;
        Ps[s] = g_P4[kp * 128 + rank * 32 + rg];
    }

    const int T0v = Tarr[grp * 2 + 0];
    const int T1v = Tarr[grp * 2 + 1];
    const int Tc  = max(T0v, T1v);

    /* ---- init: u_0 = exp(alpha0 - m), full & replicated per CTA ---- */
    float C0, C1;
    {
        int x0 = x[(grp * 2 + b) * TMAXL];
        float a[4];
        float lm = -3.402823466e38f;
        #pragma unroll
        for (int j = 0; j < 4; j++) {
            int s = il + 128 * j;
            a[j] = g_logPi[s] + g_logET[x0 * N_ST + s];
            lm = fmaxf(lm, a[j]);
        }
        #pragma unroll
        for (int o = 16; o; o >>= 1) lm = fmaxf(lm, __shfl_xor_sync(0xffffffffu, lm, o));
        if (lane == 0) red[warp] = lm;
        __syncthreads();
        const float m0 = fmaxf(fmaxf(red[0], red[1]), fmaxf(red[2], red[3]));
        const float m1 = fmaxf(fmaxf(red[4], red[5]), fmaxf(red[6], red[7]));
        C0 = m0; C1 = m1;
        const float m = b ? m1 : m0;
        float* u0b = uarr + b * U_STRIDE;
        float ls = 0.f;
        #pragma unroll
        for (int j = 0; j < 4; j++) {
            int s = il + 128 * j;
            float uv = __expf(a[j] - m);
            u0b[s] = uv;
            ls += uv;
        }
        #pragma unroll
        for (int o = 16; o; o >>= 1) ls += __shfl_xor_sync(0xffffffffu, ls, o);
        if (lane == 0) u0b[512 + (warp & 3)] = ls;
        if (il >= 4 && il < 16) u0b[512 + il] = 0.f;
        __syncthreads();
    }
    cluster.sync();   /* barrier init + everyone ready */

    unsigned ph0 = 0, ph1 = 0;

    for (int t = 0; t < Tc; ++t) {
        if (t > 0) {
            if ((t - 1) & 1) { MBARRIER_WAIT_PARITY(bar1, ph1); ph1 ^= 1; }
            else             { MBARRIER_WAIT_PARITY(bar0, ph0); ph0 ^= 1; }
        }

        const int buf = t & 1;
        float* ub0 = uarr + (buf * 2 + 0) * U_STRIDE;
        float* ub1 = uarr + (buf * 2 + 1) * U_STRIDE;

        /* S = sum of 16 partials per batch (broadcast loads) */
        float4 p0a = *(const float4*)(ub0 + 512), p0b = *(const float4*)(ub0 + 516);
        float4 p0c = *(const float4*)(ub0 + 520), p0d = *(const float4*)(ub0 + 524);
        float4 p1a = *(const float4*)(ub1 + 512), p1b = *(const float4*)(ub1 + 516);
        float4 p1c = *(const float4*)(ub1 + 520), p1d = *(const float4*)(ub1 + 524);
        const float S0 = (((p0a.x + p0a.y) + (p0a.z + p0a.w)) + ((p0b.x + p0b.y) + (p0b.z + p0b.w)))
                       + (((p0c.x + p0c.y) + (p0c.z + p0c.w)) + ((p0d.x + p0d.y) + (p0d.z + p0d.w)));
        const float S1 = (((p1a.x + p1a.y) + (p1a.z + p1a.w)) + ((p1b.x + p1b.y) + (p1b.z + p1b.w)))
                       + (((p1c.x + p1c.y) + (p1c.z + p1c.w)) + ((p1d.x + p1d.y) + (p1d.z + p1d.w)));
        C0 += __logf(S0);
        C1 += __logf(S1);

        if (rank == 0 && tid == 0) {
            if (t == T0v - 1) out[grp * 2 + 0] = C0;
            if (t == T1v - 1) out[grp * 2 + 1] = C1;
        }
        if (t == Tc - 1) break;

        /* prefetch emission for phase 2 */
        const int   xv   = x[(grp * 2 + b) * TMAXL + t + 1];
        const float em   = g_expET[xv * N_ST + iglob];
        const float invS = __frcp_rn(b ? S1 : S0);

        /* ---- dot phase: thread = (k-slice ks=warp, row-group rg=lane) ----
           4 rows x 64 k x 2 batches per thread, packed-pair FFMA2         */
        {
            const int ks = warp;
            const uint4* Pp = Ps + (ks * 32) * 32 + lane;
            const ulonglong2* U0 = (const ulonglong2*)ub0 + ks * 16;
            const ulonglong2* U1 = (const ulonglong2*)ub1 + ks * 16;

            unsigned long long accA0 = 0, accA1 = 0, accA2 = 0, accA3 = 0;
            unsigned long long accB0 = 0, accB1 = 0, accB2 = 0, accB3 = 0;

            #pragma unroll 4
            for (int kp2 = 0; kp2 < 16; ++kp2) {
                uint4 qa = Pp[(2 * kp2) * 32];
                uint4 qb = Pp[(2 * kp2 + 1) * 32];
                ulonglong2 W0 = U0[kp2];
                ulonglong2 W1 = U1[kp2];

                unsigned long long a0, a1, a2, a3;
                a0 = ((unsigned long long)qa.x << 32) | (unsigned)(qa.x << 16);
                a1 = ((unsigned long long)qa.y << 32) | (unsigned)(qa.y << 16);
                a2 = ((unsigned long long)qa.z << 32) | (unsigned)(qa.z << 16);
                a3 = ((unsigned long long)qa.w << 32) | (unsigned)(qa.w << 16);
                FMA2(accA0, a0, W0.x);  FMA2(accB0, a0, W1.x);
                FMA2(accA1, a1, W0.x);  FMA2(accB1, a1, W1.x);
                FMA2(accA2, a2, W0.x);  FMA2(accB2, a2, W1.x);
                FMA2(accA3, a3, W0.x);  FMA2(accB3, a3, W1.x);

                a0 = ((unsigned long long)qb.x << 32) | (unsigned)(qb.x << 16);
                a1 = ((unsigned long long)qb.y << 32) | (unsigned)(qb.y << 16);
                a2 = ((unsigned long long)qb.z << 32) | (unsigned)(qb.z << 16);
                a3 = ((unsigned long long)qb.w << 32) | (unsigned)(qb.w << 16);
                FMA2(accA0, a0, W0.y);  FMA2(accB0, a0, W1.y);
                FMA2(accA1, a1, W0.y);  FMA2(accB1, a1, W1.y);
                FMA2(accA2, a2, W0.y);  FMA2(accB2, a2, W1.y);
                FMA2(accA3, a3, W0.y);  FMA2(accB3, a3, W1.y);
            }

            /* collapse f32x2 pairs and store per-(ks,b) row partials */
            float4 ra, rb;
            ra.x = __uint_as_float((unsigned)accA0) + __uint_as_float((unsigned)(accA0 >> 32));
            ra.y = __uint_as_float((unsigned)accA1) + __uint_as_float((unsigned)(accA1 >> 32));
            ra.z = __uint_as_float((unsigned)accA2) + __uint_as_float((unsigned)(accA2 >> 32));
            ra.w = __uint_as_float((unsigned)accA3) + __uint_as_float((unsigned)(accA3 >> 32));
            rb.x = __uint_as_float((unsigned)accB0) + __uint_as_float((unsigned)(accB0 >> 32));
            rb.y = __uint_as_float((unsigned)accB1) + __uint_as_float((unsigned)(accB1 >> 32));
            rb.z = __uint_as_float((unsigned)accB2) + __uint_as_float((unsigned)(accB2 >> 32));
            rb.w = __uint_as_float((unsigned)accB3) + __uint_as_float((unsigned)(accB3 >> 32));
            *(float4*)&pdot[(ks * 2 + 0) * 128 + lane * 4] = ra;
            *(float4*)&pdot[(ks * 2 + 1) * 128 + lane * 4] = rb;
        }
        __syncthreads();

        /* ---- phase 2: thread = (batch b, row il) ---- */
        float d = 0.f;
        #pragma unroll
        for (int ks = 0; ks < 8; ++ks) d += pdot[(ks * 2 + b) * 128 + il];
        const float v = em * d * invS;

        float psum = v;
        #pragma unroll
        for (int o = 16; o; o >>= 1) psum += __shfl_xor_sync(0xffffffffu, psum, o);

        /* exchange slice + warp partial to all ranks (DSMEM) */
        const int nb = buf ^ 1;
        float* dst   = uarr + (nb * 2 + b) * U_STRIDE + iglob;
        float* dslot = uarr + (nb * 2 + b) * U_STRIDE + 512 + rank * 4 + (warp & 3);
        #pragma unroll
        for (int dr = 0; dr < CLUSTER_N; ++dr) {
            *cluster.map_shared_rank(dst, dr) = v;
            if (lane == 0) *cluster.map_shared_rank(dslot, dr) = psum;
        }
        __syncthreads();

        if (tid < CLUSTER_N) {
            if (t & 1) MBARRIER_ARRIVE_CLUSTER(bar1, tid);
            else       MBARRIER_ARRIVE_CLUSTER(bar0, tid);
        }
    }
}

/* ---------------- launch ---------------- */

extern "C" void kernel_launch(void* const* d_in, const int* in_sizes, int n_in,
                              void* d_out, int out_size)
{
    const float* pi = (const float*)d_in[0];
    const float* A  = (const float*)d_in[1];
    const float* E  = (const float*)d_in[2];
    const int*   x  = (const int*)d_in[3];
    const int*   T  = (const int*)d_in[4];
    float* out = (float*)d_out;

    cudaFuncSetAttribute(hmm_main, cudaFuncAttributeMaxDynamicSharedMemorySize, SMEM_TOTAL);

    prep_logpi<<<1, 256>>>(pi);
    prep_colsum<<<16, 256>>>(A);
    prep_pt<<<N_ST, 256>>>(A);
    prep_logE<<<N_ST, 256>>>(E);
    hmm_main<<<(BATCH / 2) * CLUSTER_N, THREADS, SMEM_TOTAL>>>(x, T, out);
}